// round 4
// baseline (speedup 1.0000x reference)
#include <cuda_runtime.h>
#include <cstdint>

#define Tn   100
#define Fn   64
#define Hn   5
#define OUTn 3
#define EPB  128      // batch elements per block
#define BLK  512      // 4 threads per element
#define ROWF 68       // padded floats per x row in smem

typedef unsigned long long u64;

// ---------- f32x2 packed helpers ----------
__device__ __forceinline__ u64 pack2(float lo, float hi) {
    u64 r; asm("mov.b64 %0, {%1, %2};" : "=l"(r) : "f"(lo), "f"(hi)); return r;
}
__device__ __forceinline__ void unpack2(u64 v, float& lo, float& hi) {
    asm("mov.b64 {%0, %1}, %2;" : "=f"(lo), "=f"(hi) : "l"(v));
}
__device__ __forceinline__ u64 ffma2(u64 a, u64 b, u64 c) {
    u64 d; asm("fma.rn.f32x2 %0, %1, %2, %3;" : "=l"(d) : "l"(a), "l"(b), "l"(c));
    return d;
}

__device__ __forceinline__ float tanhfast(float x) {
    float ax = fabsf(x);
    float e  = __expf(-2.0f * ax);
    float r  = __fdividef(1.0f - e, 1.0f + e);
    return copysignf(r, x);
}

// accumulate one scalar input through one padded weight row (5 used of 8)
__device__ __forceinline__ void accrow(u64& a01, u64& a23, float& z4,
                                       float v, const float4* row8) {
    float4 w  = row8[0];
    float  w4 = reinterpret_cast<const float*>(row8)[4];
    u64 vv = pack2(v, v);
    a01 = ffma2(vv, pack2(w.x, w.y), a01);
    a23 = ffma2(vv, pack2(w.z, w.w), a23);
    z4  = fmaf(v, w4, z4);
}

// gate nonlinearity + quad exchange + replicated h,c update
__device__ __forceinline__ void combine(u64 a01, u64 a23, float z4,
                                        float kmul, float affa, float affb,
                                        int lbase, int g,
                                        float* h, float* c) {
    float z[5];
    unpack2(a01, z[0], z[1]);
    unpack2(a23, z[2], z[3]);
    z[4] = z4;
    float act[5];
#pragma unroll
    for (int k = 0; k < 5; k++) {
        float y = __fdividef(1.0f, 1.0f + __expf(-kmul * z[k]));
        act[k] = fmaf(affa, y, affb);
    }
    float A0[5], A1[5], A2[5], A3[5];
#pragma unroll
    for (int k = 0; k < 5; k++) {
        A0[k] = __shfl_sync(0xffffffffu, act[k], lbase + 0);
        A1[k] = __shfl_sync(0xffffffffu, act[k], lbase + 1);
        A2[k] = __shfl_sync(0xffffffffu, act[k], lbase + 2);
        A3[k] = __shfl_sync(0xffffffffu, act[k], lbase + 3);
    }
    float cn[5];
#pragma unroll
    for (int j = 0; j < 5; j++) {
        cn[j] = fmaf(A1[j], c[j], A0[j] * A2[j]);
        c[j]  = cn[j];
    }
    // static-index select of cn[g] (g in 0..3) to avoid local-mem indexing
    float cg = (g == 0) ? cn[0] : (g == 1) ? cn[1] : (g == 2) ? cn[2] : cn[3];
    float tA = tanhfast(cg);
    float tB = tanhfast(cn[4]);
    float th[5];
#pragma unroll
    for (int j = 0; j < 4; j++) th[j] = __shfl_sync(0xffffffffu, tA, lbase + j);
    th[4] = tB;
#pragma unroll
    for (int j = 0; j < 5; j++) h[j] = A3[j] * th[j];
}

extern "C" __global__ void __launch_bounds__(BLK, 1)
lstm3_kernel(const float* __restrict__ x,
             const float* __restrict__ W1, const float* __restrict__ U1, const float* __restrict__ b1,
             const float* __restrict__ W2, const float* __restrict__ U2, const float* __restrict__ b2,
             const float* __restrict__ W3, const float* __restrict__ U3, const float* __restrict__ b3,
             const float* __restrict__ Wd, const float* __restrict__ bd,
             float* __restrict__ out)
{
    // gate-sliced weights, rows padded to 8 floats
    __shared__ __align__(16) float sW1g[4 * Fn * 8];          // [gate][feat][8]
    __shared__ __align__(16) float sRec[5 * 4 * Hn * 8];      // [mat:U1,W2,U2,W3,U3][gate][row][8]
    __shared__ __align__(16) float sBias[3 * 4 * 8];          // [layer][gate][8]
    __shared__ float sWd[Hn * OUTn];
    __shared__ float sbd[OUTn];
    extern __shared__ float xs[];                             // 2 x [EPB][ROWF]

    const int tid   = threadIdx.x;
    const int g     = tid & 3;          // gate: 0=i 1=f 2=g 3=o
    const int e     = tid >> 2;         // element within block
    const int lane  = tid & 31;
    const int lbase = lane & ~3;
    const int b0    = blockIdx.x * EPB;

    // ---- stage gate-sliced weights ----
    for (int i = tid; i < 4 * Fn * 5; i += BLK) {
        int gt = i / (Fn * 5), r = i % (Fn * 5), f = r / 5, k = r % 5;
        sW1g[(gt * Fn + f) * 8 + k] = W1[f * 20 + gt * 5 + k];
    }
    {
        const float* mats[5] = { U1, W2, U2, W3, U3 };
#pragma unroll
        for (int m = 0; m < 5; m++)
            for (int i = tid; i < 4 * Hn * 5; i += BLK) {
                int gt = i / 25, r = i % 25, rr = r / 5, k = r % 5;
                sRec[((m * 4 + gt) * Hn + rr) * 8 + k] = mats[m][rr * 20 + gt * 5 + k];
            }
        const float* bs[3] = { b1, b2, b3 };
#pragma unroll
        for (int l = 0; l < 3; l++)
            for (int i = tid; i < 4 * 5; i += BLK) {
                int gt = i / 5, k = i % 5;
                sBias[(l * 4 + gt) * 8 + k] = bs[l][gt * 5 + k];
            }
    }
    if (tid < Hn * OUTn) sWd[tid] = Wd[tid];
    if (tid < OUTn)      sbd[tid] = bd[tid];

    // ---- cp.async x loader: 128 rows x 64 floats, coalesced ----
    const int rowq = tid >> 4;   // 0..31
    const int colq = tid & 15;   // float4 index in row
    const uint32_t sm_base = (uint32_t)__cvta_generic_to_shared(xs);

#define ISSUE_X(t_, sel_)                                                           \
    do {                                                                             \
        uint32_t base_ = sm_base + (uint32_t)(sel_) * (EPB * ROWF * 4);              \
        _Pragma("unroll")                                                            \
        for (int p = 0; p < 4; p++) {                                                \
            int row_ = p * 32 + rowq;                                                \
            const float* g_ = x + ((size_t)(b0 + row_) * Tn + (t_)) * Fn + colq * 4; \
            uint32_t dst_ = base_ + (uint32_t)(row_ * ROWF * 4 + colq * 16);         \
            asm volatile("cp.async.cg.shared.global [%0], [%1], 16;"                 \
                         :: "r"(dst_), "l"(g_));                                     \
        }                                                                            \
    } while (0)

    ISSUE_X(0, 0);
    asm volatile("cp.async.commit_group;");

    // per-gate activation constants (gate 2 = tanh via 2*sig(2x)-1)
    const float kmul = (g == 2) ? 2.0f : 1.0f;
    const float affa = (g == 2) ? 2.0f : 1.0f;
    const float affb = (g == 2) ? -1.0f : 0.0f;

    float h1[Hn], c1[Hn], h2[Hn], c2[Hn], h3[Hn], c3[Hn];
#pragma unroll
    for (int j = 0; j < Hn; j++)
        h1[j] = c1[j] = h2[j] = c2[j] = h3[j] = c3[j] = 0.0f;

    const float4* wg = reinterpret_cast<const float4*>(&sW1g[g * Fn * 8]); // 2 float4 per row

    for (int t = 0; t < Tn; t++) {
        const int cur = t & 1;
        asm volatile("cp.async.wait_group 0;");
        __syncthreads();              // buffer 'cur' visible; prior reads of 'nxt' done
        if (t + 1 < Tn) {
            ISSUE_X(t + 1, cur ^ 1);
            asm volatile("cp.async.commit_group;");
        }

        const float4* xr4 =
            reinterpret_cast<const float4*>(xs + cur * (EPB * ROWF) + e * ROWF);

        // ----- layer 1 -----
        u64 a01, a23; float z4;
        {
            const float* bp = &sBias[(0 * 4 + g) * 8];
            a01 = pack2(bp[0], bp[1]); a23 = pack2(bp[2], bp[3]); z4 = bp[4];
        }
#pragma unroll
        for (int q = 0; q < 16; q++) {
            float4 xv = xr4[q];
            accrow(a01, a23, z4, xv.x, wg + (4 * q + 0) * 2);
            accrow(a01, a23, z4, xv.y, wg + (4 * q + 1) * 2);
            accrow(a01, a23, z4, xv.z, wg + (4 * q + 2) * 2);
            accrow(a01, a23, z4, xv.w, wg + (4 * q + 3) * 2);
        }
        {
            const float4* u1 = reinterpret_cast<const float4*>(&sRec[((0 * 4 + g) * Hn) * 8]);
#pragma unroll
            for (int j = 0; j < Hn; j++) accrow(a01, a23, z4, h1[j], u1 + j * 2);
        }
        combine(a01, a23, z4, kmul, affa, affb, lbase, g, h1, c1);

        // ----- layer 2 -----
        {
            const float* bp = &sBias[(1 * 4 + g) * 8];
            a01 = pack2(bp[0], bp[1]); a23 = pack2(bp[2], bp[3]); z4 = bp[4];
            const float4* w2 = reinterpret_cast<const float4*>(&sRec[((1 * 4 + g) * Hn) * 8]);
            const float4* u2 = reinterpret_cast<const float4*>(&sRec[((2 * 4 + g) * Hn) * 8]);
#pragma unroll
            for (int j = 0; j < Hn; j++) accrow(a01, a23, z4, h1[j], w2 + j * 2);
#pragma unroll
            for (int j = 0; j < Hn; j++) accrow(a01, a23, z4, h2[j], u2 + j * 2);
        }
        combine(a01, a23, z4, kmul, affa, affb, lbase, g, h2, c2);

        // ----- layer 3 -----
        {
            const float* bp = &sBias[(2 * 4 + g) * 8];
            a01 = pack2(bp[0], bp[1]); a23 = pack2(bp[2], bp[3]); z4 = bp[4];
            const float4* w3 = reinterpret_cast<const float4*>(&sRec[((3 * 4 + g) * Hn) * 8]);
            const float4* u3 = reinterpret_cast<const float4*>(&sRec[((4 * 4 + g) * Hn) * 8]);
#pragma unroll
            for (int j = 0; j < Hn; j++) accrow(a01, a23, z4, h2[j], w3 + j * 2);
#pragma unroll
            for (int j = 0; j < Hn; j++) accrow(a01, a23, z4, h3[j], u3 + j * 2);
        }
        combine(a01, a23, z4, kmul, affa, affb, lbase, g, h3, c3);
    }

    // ---- dense head (gate-0 thread of each quad writes) ----
    if (g == 0) {
        const int b = b0 + e;
#pragma unroll
        for (int oc = 0; oc < OUTn; oc++) {
            float a = sbd[oc];
#pragma unroll
            for (int j = 0; j < Hn; j++) a = fmaf(h3[j], sWd[j * OUTn + oc], a);
            out[(size_t)b * OUTn + oc] = a;
        }
    }
#undef ISSUE_X
}

extern "C" void kernel_launch(void* const* d_in, const int* in_sizes, int n_in,
                              void* d_out, int out_size)
{
    const float* x  = (const float*)d_in[0];
    const float* W1 = (const float*)d_in[1];
    const float* U1 = (const float*)d_in[2];
    const float* b1 = (const float*)d_in[3];
    const float* W2 = (const float*)d_in[4];
    const float* U2 = (const float*)d_in[5];
    const float* b2 = (const float*)d_in[6];
    const float* W3 = (const float*)d_in[7];
    const float* U3 = (const float*)d_in[8];
    const float* b3 = (const float*)d_in[9];
    const float* Wd = (const float*)d_in[10];
    const float* bd = (const float*)d_in[11];
    float* out = (float*)d_out;

    const int B    = in_sizes[0] / (Tn * Fn);   // 16384
    const int smem = 2 * EPB * ROWF * 4;        // 69632 B

    cudaFuncSetAttribute(lstm3_kernel, cudaFuncAttributeMaxDynamicSharedMemorySize, smem);
    lstm3_kernel<<<B / EPB, BLK, smem>>>(x, W1, U1, b1, W2, U2, b2,
                                         W3, U3, b3, Wd, bd, out);
}

// round 6
// speedup vs baseline: 2.1250x; 2.1250x over previous
#include <cuda_runtime.h>
#include <cstdint>

#define Bn   16384
#define Tn   100
#define Fn   64
#define Hn   5
#define OUTn 3

typedef unsigned long long u64;

// scratch: XZ[t][k][b] = (x @ W1 + b1), t-major, batch-contiguous
__device__ float g_xz[(size_t)Tn * 20 * Bn];

// ---------- f32x2 packed helpers ----------
__device__ __forceinline__ u64 pack2(float lo, float hi) {
    u64 r; asm("mov.b64 %0, {%1, %2};" : "=l"(r) : "f"(lo), "f"(hi)); return r;
}
__device__ __forceinline__ void unpack2(u64 v, float& lo, float& hi) {
    asm("mov.b64 {%0, %1}, %2;" : "=f"(lo), "=f"(hi) : "l"(v));
}
__device__ __forceinline__ u64 ffma2(u64 a, u64 b, u64 c) {
    u64 d; asm("fma.rn.f32x2 %0, %1, %2, %3;" : "=l"(d) : "l"(a), "l"(b), "l"(c));
    return d;
}
__device__ __forceinline__ float ex2a(float a) {
    float r; asm("ex2.approx.f32 %0, %1;" : "=f"(r) : "f"(a)); return r;
}
__device__ __forceinline__ float rcpa(float a) {
    float r; asm("rcp.approx.f32 %0, %1;" : "=f"(r) : "f"(a)); return r;
}

// accumulate scalar v through a 10-pair (20-wide) weight row
__device__ __forceinline__ void acc_row(u64* acc, float v, const u64* row) {
    u64 vv = pack2(v, v);
    const ulonglong2* r2 = reinterpret_cast<const ulonglong2*>(row);
#pragma unroll
    for (int p = 0; p < 5; p++) {
        ulonglong2 w = r2[p];
        acc[2 * p]     = ffma2(vv, w.x, acc[2 * p]);
        acc[2 * p + 1] = ffma2(vv, w.y, acc[2 * p + 1]);
    }
}

// batched 5-way reciprocal (Montgomery): 1 RCP for 5 divisions
__device__ __forceinline__ void rcp5(const float* d, float* inv) {
    float p1 = d[0] * d[1];
    float p2 = p1 * d[2];
    float p3 = p2 * d[3];
    float p4 = p3 * d[4];
    float r  = rcpa(p4);
    inv[4] = r * p3;  r *= d[4];
    inv[3] = r * p2;  r *= d[3];
    inv[2] = r * p1;  r *= d[2];
    inv[1] = r * d[0];
    inv[0] = r * d[1];
}

// z[20] (i,f,g,o blocks of 5) -> update h[5], c[5]
__device__ __forceinline__ void lstm_gates(const float* z, float* h, float* c) {
    const float L2E = 1.4426950408889634f;
    float d[20], inv[20];
#pragma unroll
    for (int k = 0; k < 20; k++) {
        float s = (k >= 10 && k < 15) ? (2.0f * L2E) : L2E;  // tanh gate: 2*sig(2x)-1
        float a = fminf(-s * z[k], 20.0f);                   // clamp: keep prod of 5 finite
        d[k] = 1.0f + ex2a(a);
    }
    rcp5(d, inv); rcp5(d + 5, inv + 5); rcp5(d + 10, inv + 10); rcp5(d + 15, inv + 15);
    float cn[5], dd[5], th[5];
#pragma unroll
    for (int j = 0; j < 5; j++) {
        float gg = fmaf(2.0f, inv[10 + j], -1.0f);
        cn[j] = fmaf(inv[5 + j], c[j], inv[j] * gg);
        c[j]  = cn[j];
        float a = fminf(-2.0f * L2E * cn[j], 20.0f);
        dd[j] = 1.0f + ex2a(a);
    }
    rcp5(dd, th);
#pragma unroll
    for (int j = 0; j < 5; j++) h[j] = inv[15 + j] * fmaf(2.0f, th[j], -1.0f);
}

// ============================================================
// Phase 1: XZ[t][k][b] = x[b][t][:] @ W1 + b1
// tile: 32 b  x 4 t per block, 128 threads (warp = one t, lane = one b)
// ============================================================
#define P1_BC   32
#define P1_TC   4
#define P1_BLK  128
#define CHUNK   276   // floats per b-chunk (4 rows x 68 pad + 4) = 69 x 16B (odd -> conflict-free)

extern "C" __global__ void __launch_bounds__(P1_BLK, 1)
p1_proj(const float* __restrict__ x, const float* __restrict__ W1,
        const float* __restrict__ b1)
{
    __shared__ __align__(16) float xsh[P1_BC * CHUNK];
    __shared__ __align__(16) u64   w1p[Fn * 10];
    __shared__ __align__(16) u64   b1p[10];

    const int tid = threadIdx.x;
    const int tile_b = blockIdx.x % (Bn / P1_BC);
    const int tile_t = blockIdx.x / (Bn / P1_BC);
    const int b0 = tile_b * P1_BC;
    const int t0 = tile_t * P1_TC;

    // stage W1 (64x20) as k-pairs, and b1
    for (int i = tid; i < Fn * 10; i += P1_BLK) {
        float2 w = reinterpret_cast<const float2*>(W1)[i];
        w1p[i] = pack2(w.x, w.y);
    }
    if (tid < 10) {
        float2 w = reinterpret_cast<const float2*>(b1)[tid];
        b1p[tid] = pack2(w.x, w.y);
    }

    // stage x rows via cp.async: 32 b x 4 t x 64 floats
    const uint32_t smx = (uint32_t)__cvta_generic_to_shared(xsh);
#pragma unroll
    for (int r = 0; r < 16; r++) {
        int s  = tid + r * P1_BLK;          // 0..2047
        int bb = s >> 6;                    // 0..31
        int dt = (s >> 4) & 3;              // 0..3
        int q  = s & 15;                    // 0..15 float4 within row
        const float* src = x + ((size_t)(b0 + bb) * Tn + (t0 + dt)) * Fn + q * 4;
        uint32_t dst = smx + (uint32_t)((bb * CHUNK + dt * 68 + q * 4) * 4);
        asm volatile("cp.async.cg.shared.global [%0], [%1], 16;" :: "r"(dst), "l"(src));
    }
    asm volatile("cp.async.commit_group;");
    asm volatile("cp.async.wait_group 0;");
    __syncthreads();

    const int lane = tid & 31;
    const int dt   = tid >> 5;
    const int bg   = b0 + lane;
    const float4* row = reinterpret_cast<const float4*>(xsh + lane * CHUNK + dt * 68);

    u64 acc[10];
#pragma unroll
    for (int p = 0; p < 10; p++) acc[p] = b1p[p];

#pragma unroll
    for (int q = 0; q < 16; q++) {
        float4 v = row[q];
        acc_row(acc, v.x, &w1p[(4 * q + 0) * 10]);
        acc_row(acc, v.y, &w1p[(4 * q + 1) * 10]);
        acc_row(acc, v.z, &w1p[(4 * q + 2) * 10]);
        acc_row(acc, v.w, &w1p[(4 * q + 3) * 10]);
    }

    float z[20];
#pragma unroll
    for (int p = 0; p < 10; p++) unpack2(acc[p], z[2 * p], z[2 * p + 1]);

    float* outp = g_xz + ((size_t)(t0 + dt) * 20) * Bn + bg;
#pragma unroll
    for (int k = 0; k < 20; k++) outp[(size_t)k * Bn] = z[k];   // coalesced across lanes
}

// ============================================================
// Phase 2: recurrence, 1 thread per batch element
// ============================================================
#define P2_BLK 128

extern "C" __global__ void __launch_bounds__(P2_BLK, 1)
p2_rec(const float* __restrict__ U1,
       const float* __restrict__ W2, const float* __restrict__ U2, const float* __restrict__ b2,
       const float* __restrict__ W3, const float* __restrict__ U3, const float* __restrict__ b3,
       const float* __restrict__ Wd, const float* __restrict__ bd,
       float* __restrict__ out)
{
    __shared__ __align__(16) u64 rec[5 * Hn * 10];   // [mat: U1,W2,U2,W3,U3][j][pair]

    const int tid = threadIdx.x;
    {
        const float* mats[5] = { U1, W2, U2, W3, U3 };
        for (int i = tid; i < 5 * Hn * 10; i += P2_BLK) {
            int m = i / (Hn * 10);
            int r = i % (Hn * 10);
            float2 w = reinterpret_cast<const float2*>(mats[m])[r];
            rec[i] = pack2(w.x, w.y);
        }
    }
    __syncthreads();

    const int b = blockIdx.x * P2_BLK + tid;

    u64 b2p[10], b3p[10];
#pragma unroll
    for (int p = 0; p < 10; p++) {
        float2 w2 = reinterpret_cast<const float2*>(b2)[p];
        float2 w3 = reinterpret_cast<const float2*>(b3)[p];
        b2p[p] = pack2(w2.x, w2.y);
        b3p[p] = pack2(w3.x, w3.y);
    }

    float h1[Hn], c1[Hn], h2[Hn], c2[Hn], h3[Hn], c3[Hn];
#pragma unroll
    for (int j = 0; j < Hn; j++)
        h1[j] = c1[j] = h2[j] = c2[j] = h3[j] = c3[j] = 0.0f;

    float zc[20], zn[20];
#pragma unroll
    for (int k = 0; k < 20; k++) zc[k] = g_xz[(size_t)k * Bn + b];

    for (int t = 0; t < Tn; t++) {
        if (t + 1 < Tn) {
            const float* np = g_xz + ((size_t)(t + 1) * 20) * Bn + b;
#pragma unroll
            for (int k = 0; k < 20; k++) zn[k] = np[(size_t)k * Bn];
        }

        u64 acc[10];
        float z[20];

        // ----- layer 1: z = xz + h1 @ U1 -----
#pragma unroll
        for (int p = 0; p < 10; p++) acc[p] = pack2(zc[2 * p], zc[2 * p + 1]);
#pragma unroll
        for (int j = 0; j < Hn; j++) acc_row(acc, h1[j], &rec[(0 * Hn + j) * 10]);
#pragma unroll
        for (int p = 0; p < 10; p++) unpack2(acc[p], z[2 * p], z[2 * p + 1]);
        lstm_gates(z, h1, c1);

        // ----- layer 2: z = b2 + h1 @ W2 + h2 @ U2 -----
#pragma unroll
        for (int p = 0; p < 10; p++) acc[p] = b2p[p];
#pragma unroll
        for (int j = 0; j < Hn; j++) acc_row(acc, h1[j], &rec[(1 * Hn + j) * 10]);
#pragma unroll
        for (int j = 0; j < Hn; j++) acc_row(acc, h2[j], &rec[(2 * Hn + j) * 10]);
#pragma unroll
        for (int p = 0; p < 10; p++) unpack2(acc[p], z[2 * p], z[2 * p + 1]);
        lstm_gates(z, h2, c2);

        // ----- layer 3: z = b3 + h2 @ W3 + h3 @ U3 -----
#pragma unroll
        for (int p = 0; p < 10; p++) acc[p] = b3p[p];
#pragma unroll
        for (int j = 0; j < Hn; j++) acc_row(acc, h2[j], &rec[(3 * Hn + j) * 10]);
#pragma unroll
        for (int j = 0; j < Hn; j++) acc_row(acc, h3[j], &rec[(4 * Hn + j) * 10]);
#pragma unroll
        for (int p = 0; p < 10; p++) unpack2(acc[p], z[2 * p], z[2 * p + 1]);
        lstm_gates(z, h3, c3);

#pragma unroll
        for (int k = 0; k < 20; k++) zc[k] = zn[k];
    }

    // ----- dense head -----
#pragma unroll
    for (int oc = 0; oc < OUTn; oc++) {
        float a = bd[oc];
#pragma unroll
        for (int j = 0; j < Hn; j++) a = fmaf(h3[j], Wd[j * OUTn + oc], a);
        out[(size_t)b * OUTn + oc] = a;
    }
}

extern "C" void kernel_launch(void* const* d_in, const int* in_sizes, int n_in,
                              void* d_out, int out_size)
{
    const float* x  = (const float*)d_in[0];
    const float* W1 = (const float*)d_in[1];
    const float* U1 = (const float*)d_in[2];
    const float* b1 = (const float*)d_in[3];
    const float* W2 = (const float*)d_in[4];
    const float* U2 = (const float*)d_in[5];
    const float* b2 = (const float*)d_in[6];
    const float* W3 = (const float*)d_in[7];
    const float* U3 = (const float*)d_in[8];
    const float* b3 = (const float*)d_in[9];
    const float* Wd = (const float*)d_in[10];
    const float* bd = (const float*)d_in[11];
    float* out = (float*)d_out;

    p1_proj<<<(Bn / P1_BC) * (Tn / P1_TC), P1_BLK>>>(x, W1, b1);
    p2_rec<<<Bn / P2_BLK, P2_BLK>>>(U1, W2, U2, b2, W3, U3, b3, Wd, bd, out);
}

// round 10
// speedup vs baseline: 3.8975x; 1.8341x over previous
#include <cuda_runtime.h>
#include <cstdint>

#define Bn   16384
#define Tn   100
#define Fn   64
#define Hn   5
#define OUTn 3

typedef unsigned long long u64;

// scratch: XZ[t][k][b] = (x @ W1 + b1), t-major, batch-contiguous
__device__ float g_xz[(size_t)Tn * 20 * Bn];

// ---------- f32x2 packed helpers ----------
__device__ __forceinline__ u64 pack2(float lo, float hi) {
    u64 r; asm("mov.b64 %0, {%1, %2};" : "=l"(r) : "f"(lo), "f"(hi)); return r;
}
__device__ __forceinline__ void unpack2(u64 v, float& lo, float& hi) {
    asm("mov.b64 {%0, %1}, %2;" : "=f"(lo), "=f"(hi) : "l"(v));
}
__device__ __forceinline__ u64 ffma2(u64 a, u64 b, u64 c) {
    u64 d; asm("fma.rn.f32x2 %0, %1, %2, %3;" : "=l"(d) : "l"(a), "l"(b), "l"(c));
    return d;
}

__device__ __forceinline__ float tanhfast(float x) {
    float ax = fabsf(x);
    float e  = __expf(-2.0f * ax);
    float r  = __fdividef(1.0f - e, 1.0f + e);
    return copysignf(r, x);
}

// ============================================================
// Phase 1: XZ[t][k][b] = x[b][t][:] @ W1 + b1   (unchanged, ~124us measured)
// ============================================================
#define P1_BC   32
#define P1_TC   4
#define P1_BLK  128
#define CHUNK   276

__device__ __forceinline__ void acc_row20(u64* acc, float v, const u64* row) {
    u64 vv = pack2(v, v);
    const ulonglong2* r2 = reinterpret_cast<const ulonglong2*>(row);
#pragma unroll
    for (int p = 0; p < 5; p++) {
        ulonglong2 w = r2[p];
        acc[2 * p]     = ffma2(vv, w.x, acc[2 * p]);
        acc[2 * p + 1] = ffma2(vv, w.y, acc[2 * p + 1]);
    }
}

extern "C" __global__ void __launch_bounds__(P1_BLK, 1)
p1_proj(const float* __restrict__ x, const float* __restrict__ W1,
        const float* __restrict__ b1)
{
    __shared__ __align__(16) float xsh[P1_BC * CHUNK];
    __shared__ __align__(16) u64   w1p[Fn * 10];
    __shared__ __align__(16) u64   b1p[10];

    const int tid = threadIdx.x;
    const int tile_b = blockIdx.x % (Bn / P1_BC);
    const int tile_t = blockIdx.x / (Bn / P1_BC);
    const int b0 = tile_b * P1_BC;
    const int t0 = tile_t * P1_TC;

    for (int i = tid; i < Fn * 10; i += P1_BLK) {
        float2 w = reinterpret_cast<const float2*>(W1)[i];
        w1p[i] = pack2(w.x, w.y);
    }
    if (tid < 10) {
        float2 w = reinterpret_cast<const float2*>(b1)[tid];
        b1p[tid] = pack2(w.x, w.y);
    }

    const uint32_t smx = (uint32_t)__cvta_generic_to_shared(xsh);
#pragma unroll
    for (int r = 0; r < 16; r++) {
        int s  = tid + r * P1_BLK;
        int bb = s >> 6;
        int dt = (s >> 4) & 3;
        int q  = s & 15;
        const float* src = x + ((size_t)(b0 + bb) * Tn + (t0 + dt)) * Fn + q * 4;
        uint32_t dst = smx + (uint32_t)((bb * CHUNK + dt * 68 + q * 4) * 4);
        asm volatile("cp.async.cg.shared.global [%0], [%1], 16;" :: "r"(dst), "l"(src));
    }
    asm volatile("cp.async.commit_group;");
    asm volatile("cp.async.wait_group 0;");
    __syncthreads();

    const int lane = tid & 31;
    const int dt   = tid >> 5;
    const int bg   = b0 + lane;
    const float4* row = reinterpret_cast<const float4*>(xsh + lane * CHUNK + dt * 68);

    u64 acc[10];
#pragma unroll
    for (int p = 0; p < 10; p++) acc[p] = b1p[p];

#pragma unroll
    for (int q = 0; q < 16; q++) {
        float4 v = row[q];
        acc_row20(acc, v.x, &w1p[(4 * q + 0) * 10]);
        acc_row20(acc, v.y, &w1p[(4 * q + 1) * 10]);
        acc_row20(acc, v.z, &w1p[(4 * q + 2) * 10]);
        acc_row20(acc, v.w, &w1p[(4 * q + 3) * 10]);
    }

    float z[20];
#pragma unroll
    for (int p = 0; p < 10; p++) unpack2(acc[p], z[2 * p], z[2 * p + 1]);

    float* outp = g_xz + ((size_t)(t0 + dt) * 20) * Bn + bg;
#pragma unroll
    for (int k = 0; k < 20; k++) outp[(size_t)k * Bn] = z[k];
}

// ============================================================
// Phase 2: recurrence, 4 threads per element (one gate each)
// Exchange = R1's verified combine() (rel_err 3.9e-7 in Round 4)
// ============================================================
#define P2_BLK 128   // 32 elements per block, grid = 512

// accumulate h-scalar through this thread's 5-wide gate slice of a row
__device__ __forceinline__ void accq(u64& a01, u64& a23, float& a4,
                                     float v, const float* row8) {
    float4 w  = *reinterpret_cast<const float4*>(row8);
    float  w4 = row8[4];
    u64 vv = pack2(v, v);
    a01 = ffma2(vv, pack2(w.x, w.y), a01);
    a23 = ffma2(vv, pack2(w.z, w.w), a23);
    a4  = fmaf(v, w4, a4);
}

// gate nonlinearity + quad exchange + replicated h,c update (VERIFIED in R4 bench)
__device__ __forceinline__ void combine(u64 a01, u64 a23, float z4,
                                        float kmul, float affa, float affb,
                                        int lbase, int g,
                                        float* h, float* c) {
    float z[5];
    unpack2(a01, z[0], z[1]);
    unpack2(a23, z[2], z[3]);
    z[4] = z4;
    float act[5];
#pragma unroll
    for (int k = 0; k < 5; k++) {
        float y = __fdividef(1.0f, 1.0f + __expf(-kmul * z[k]));
        act[k] = fmaf(affa, y, affb);
    }
    float A0[5], A1[5], A2[5], A3[5];
#pragma unroll
    for (int k = 0; k < 5; k++) {
        A0[k] = __shfl_sync(0xffffffffu, act[k], lbase + 0);
        A1[k] = __shfl_sync(0xffffffffu, act[k], lbase + 1);
        A2[k] = __shfl_sync(0xffffffffu, act[k], lbase + 2);
        A3[k] = __shfl_sync(0xffffffffu, act[k], lbase + 3);
    }
    float cn[5];
#pragma unroll
    for (int j = 0; j < 5; j++) {
        cn[j] = fmaf(A1[j], c[j], A0[j] * A2[j]);
        c[j]  = cn[j];
    }
    float cg = (g == 0) ? cn[0] : (g == 1) ? cn[1] : (g == 2) ? cn[2] : cn[3];
    float tA = tanhfast(cg);
    float tB = tanhfast(cn[4]);
    float th[5];
#pragma unroll
    for (int j = 0; j < 4; j++) th[j] = __shfl_sync(0xffffffffu, tA, lbase + j);
    th[4] = tB;
#pragma unroll
    for (int j = 0; j < 5; j++) h[j] = A3[j] * th[j];
}

extern "C" __global__ void __launch_bounds__(P2_BLK, 4)
p2_rec(const float* __restrict__ U1,
       const float* __restrict__ W2, const float* __restrict__ U2, const float* __restrict__ b2,
       const float* __restrict__ W3, const float* __restrict__ U3, const float* __restrict__ b3,
       const float* __restrict__ Wd, const float* __restrict__ bd,
       float* __restrict__ out)
{
    // gate-sliced recurrent weights: [mat 0..4][gate][row][8]
    __shared__ __align__(16) float sw[5 * 4 * Hn * 8];

    const int tid   = threadIdx.x;
    const int g     = tid & 3;
    const int e     = tid >> 2;
    const int lane  = tid & 31;
    const int lbase = lane & ~3;
    const int b     = blockIdx.x * (P2_BLK / 4) + e;

    {
        const float* mats[5] = { U1, W2, U2, W3, U3 };
        for (int i = tid; i < 5 * 4 * Hn * 5; i += P2_BLK) {
            int m  = i / 100;
            int r_ = i % 100;
            int gt = r_ / 25;
            int rr = (r_ % 25) / 5;
            int k  = r_ % 5;
            sw[((m * 4 + gt) * Hn + rr) * 8 + k] = mats[m][rr * 20 + gt * 5 + k];
        }
    }
    __syncthreads();

    // per-gate activation constants (gate 2 = tanh via 2*sig(2x)-1) — R1 convention
    const float kmul = (g == 2) ? 2.0f : 1.0f;
    const float affa = (g == 2) ? 2.0f : 1.0f;
    const float affb = (g == 2) ? -1.0f : 0.0f;

    // bias slices (own gate)
    float b2s[5], b3s[5];
#pragma unroll
    for (int k = 0; k < 5; k++) { b2s[k] = b2[g * 5 + k]; b3s[k] = b3[g * 5 + k]; }

    float h1[Hn], c1[Hn], h2[Hn], c2[Hn], h3[Hn], c3[Hn];
#pragma unroll
    for (int j = 0; j < Hn; j++)
        h1[j] = c1[j] = h2[j] = c2[j] = h3[j] = c3[j] = 0.0f;

    float zc[5], zn[5];
#pragma unroll
    for (int k = 0; k < 5; k++) zc[k] = g_xz[(size_t)(g * 5 + k) * Bn + b];

    for (int t = 0; t < Tn; t++) {
        if (t + 1 < Tn) {
            const float* np = g_xz + ((size_t)(t + 1) * 20 + g * 5) * Bn + b;
#pragma unroll
            for (int k = 0; k < 5; k++) zn[k] = np[(size_t)k * Bn];
        }

        u64 a01, a23; float a4;

        // ----- layer 1: z = xz + h1 @ U1(slice) -----
        a01 = pack2(zc[0], zc[1]); a23 = pack2(zc[2], zc[3]); a4 = zc[4];
#pragma unroll
        for (int j = 0; j < Hn; j++) accq(a01, a23, a4, h1[j], &sw[((0 * 4 + g) * Hn + j) * 8]);
        combine(a01, a23, a4, kmul, affa, affb, lbase, g, h1, c1);

        // ----- layer 2 -----
        a01 = pack2(b2s[0], b2s[1]); a23 = pack2(b2s[2], b2s[3]); a4 = b2s[4];
#pragma unroll
        for (int j = 0; j < Hn; j++) accq(a01, a23, a4, h1[j], &sw[((1 * 4 + g) * Hn + j) * 8]);
#pragma unroll
        for (int j = 0; j < Hn; j++) accq(a01, a23, a4, h2[j], &sw[((2 * 4 + g) * Hn + j) * 8]);
        combine(a01, a23, a4, kmul, affa, affb, lbase, g, h2, c2);

        // ----- layer 3 -----
        a01 = pack2(b3s[0], b3s[1]); a23 = pack2(b3s[2], b3s[3]); a4 = b3s[4];
#pragma unroll
        for (int j = 0; j < Hn; j++) accq(a01, a23, a4, h2[j], &sw[((3 * 4 + g) * Hn + j) * 8]);
#pragma unroll
        for (int j = 0; j < Hn; j++) accq(a01, a23, a4, h3[j], &sw[((4 * 4 + g) * Hn + j) * 8]);
        combine(a01, a23, a4, kmul, affa, affb, lbase, g, h3, c3);

#pragma unroll
        for (int k = 0; k < 5; k++) zc[k] = zn[k];
    }

    // ----- dense head (gate-0 thread writes; h3 replicated) -----
    if (g == 0) {
#pragma unroll
        for (int oc = 0; oc < OUTn; oc++) {
            float a = bd[oc];
#pragma unroll
            for (int j = 0; j < Hn; j++) a = fmaf(h3[j], Wd[j * OUTn + oc], a);
            out[(size_t)b * OUTn + oc] = a;
        }
    }
}

extern "C" void kernel_launch(void* const* d_in, const int* in_sizes, int n_in,
                              void* d_out, int out_size)
{
    const float* x  = (const float*)d_in[0];
    const float* W1 = (const float*)d_in[1];
    const float* U1 = (const float*)d_in[2];
    const float* b1 = (const float*)d_in[3];
    const float* W2 = (const float*)d_in[4];
    const float* U2 = (const float*)d_in[5];
    const float* b2 = (const float*)d_in[6];
    const float* W3 = (const float*)d_in[7];
    const float* U3 = (const float*)d_in[8];
    const float* b3 = (const float*)d_in[9];
    const float* Wd = (const float*)d_in[10];
    const float* bd = (const float*)d_in[11];
    float* out = (float*)d_out;

    p1_proj<<<(Bn / P1_BC) * (Tn / P1_TC), P1_BLK>>>(x, W1, b1);
    p2_rec<<<(Bn * 4) / P2_BLK, P2_BLK>>>(U1, W2, U2, b2, W3, U3, b3, Wd, bd, out);
}